// round 3
// baseline (speedup 1.0000x reference)
#include <cuda_runtime.h>
#include <cstdint>

#define B_    128
#define T_    32
#define DIN   1536
#define HID   1024
#define NCAT  32

// Scratch (device globals — allocation is forbidden)
__device__ float g_hidden[B_ * T_ * HID];   // 16 MB fp32 hidden activations
__device__ int   g_perm[B_];                // batches sorted by category

// ---------------------------------------------------------------------------
// Pre-pass: counting sort of batch indices by category (128 elems, trivial).
// Gives L2 temporal locality: same-category CTAs run adjacently and share
// their weight tiles in L2 instead of re-reading HBM per batch.
// ---------------------------------------------------------------------------
__global__ void build_perm_kernel(const int* __restrict__ cat_ids) {
    if (threadIdx.x == 0 && blockIdx.x == 0) {
        int cnt[NCAT];
        #pragma unroll
        for (int c = 0; c < NCAT; c++) cnt[c] = 0;
        for (int i = 0; i < B_; i++) cnt[cat_ids[i]]++;
        int off[NCAT]; int s = 0;
        #pragma unroll
        for (int c = 0; c < NCAT; c++) { off[c] = s; s += cnt[c]; }
        for (int i = 0; i < B_; i++) {
            int c = cat_ids[i];
            g_perm[off[c]++] = i;
        }
    }
}

__device__ __forceinline__ uint32_t f2tf32(float f) {
    uint32_t r;
    asm("cvt.rna.tf32.f32 %0, %1;" : "=r"(r) : "f"(f));
    return r;
}

// ---------------------------------------------------------------------------
// One layer: out(B,T,1024) = act( in(B,T,KDIM) @ W[cat](KDIM,1024) + b[cat] )
// Block: 32x64 output tile (one batch = 32 rows), 256 threads = 8 warps in a
// 2(M) x 4(N) layout; each warp owns a 16x16 subtile via 2x m16n8k8 tf32 mma.
// ---------------------------------------------------------------------------
template <int KDIM, bool RELU, bool IN_SCRATCH, bool OUT_SCRATCH>
__global__ __launch_bounds__(256)
void catmlp_gemm(const float* __restrict__ gin,
                 const float* __restrict__ W,     // (C, KDIM, 1024)
                 const float* __restrict__ bias,  // (C, 1024)
                 const int*   __restrict__ cat_ids,
                 float* __restrict__ gout)
{
    constexpr int NOUT = 1024;
    const int batch = g_perm[blockIdx.x];
    const int n0    = blockIdx.y * 64;
    const int c     = cat_ids[batch];

    const float* A_in = (IN_SCRATCH ? g_hidden : gin) + (size_t)batch * T_ * KDIM;
    const float* Bw   = W + (size_t)c * KDIM * NOUT;

    __shared__ uint32_t As[32][33];   // [row][k]  (+1 pad)
    __shared__ uint32_t Bs[32][68];   // [k][n]    (+4 pad)

    const int tid  = threadIdx.x;
    const int wid  = tid >> 5;
    const int lane = tid & 31;
    const int wm   = (wid >> 2) << 4;   // warp row offset   (0 / 16)
    const int wn   = (wid & 3) << 4;    // warp col offset   (0/16/32/48)
    const int lg   = lane >> 2;         // lane / 4
    const int lr   = lane & 3;          // lane % 4

    float acc[2][4] = {{0.f,0.f,0.f,0.f},{0.f,0.f,0.f,0.f}};

    for (int k0 = 0; k0 < KDIM; k0 += 32) {
        // Stage A tile: 32 rows x 32 k  (1024 floats, 4/thread, float4)
        {
            const int r  = tid >> 3;
            const int kc = (tid & 7) << 2;
            float4 v = *reinterpret_cast<const float4*>(A_in + (size_t)r * KDIM + k0 + kc);
            As[r][kc + 0] = f2tf32(v.x);
            As[r][kc + 1] = f2tf32(v.y);
            As[r][kc + 2] = f2tf32(v.z);
            As[r][kc + 3] = f2tf32(v.w);
        }
        // Stage B tile: 32 k x 64 n  (2048 floats, 8/thread, 2x float4)
        #pragma unroll
        for (int it = 0; it < 2; it++) {
            const int idx = tid + it * 256;
            const int r   = idx >> 4;
            const int vc  = (idx & 15) << 2;
            float4 v = *reinterpret_cast<const float4*>(Bw + (size_t)(k0 + r) * NOUT + n0 + vc);
            Bs[r][vc + 0] = f2tf32(v.x);
            Bs[r][vc + 1] = f2tf32(v.y);
            Bs[r][vc + 2] = f2tf32(v.z);
            Bs[r][vc + 3] = f2tf32(v.w);
        }
        __syncthreads();

        #pragma unroll
        for (int ks = 0; ks < 32; ks += 8) {
            uint32_t a0 = As[wm + lg     ][ks + lr    ];
            uint32_t a1 = As[wm + lg + 8 ][ks + lr    ];
            uint32_t a2 = As[wm + lg     ][ks + lr + 4];
            uint32_t a3 = As[wm + lg + 8 ][ks + lr + 4];
            #pragma unroll
            for (int nt = 0; nt < 2; nt++) {
                uint32_t b0 = Bs[ks + lr    ][wn + nt * 8 + lg];
                uint32_t b1 = Bs[ks + lr + 4][wn + nt * 8 + lg];
                asm volatile(
                    "mma.sync.aligned.m16n8k8.row.col.f32.tf32.tf32.f32 "
                    "{%0,%1,%2,%3}, {%4,%5,%6,%7}, {%8,%9}, {%0,%1,%2,%3};"
                    : "+f"(acc[nt][0]), "+f"(acc[nt][1]),
                      "+f"(acc[nt][2]), "+f"(acc[nt][3])
                    : "r"(a0), "r"(a1), "r"(a2), "r"(a3),
                      "r"(b0), "r"(b1));
            }
        }
        __syncthreads();
    }

    // Epilogue: + bias, optional ReLU, write fp32
    const float* bv = bias + (size_t)c * NOUT + n0;
    float* O = (OUT_SCRATCH ? g_hidden : gout) + (size_t)batch * T_ * NOUT + n0;
    const int row = wm + lg;
    #pragma unroll
    for (int nt = 0; nt < 2; nt++) {
        const int col = wn + nt * 8 + (lr << 1);
        float bc0 = bv[col], bc1 = bv[col + 1];
        float v0 = acc[nt][0] + bc0;
        float v1 = acc[nt][1] + bc1;
        float v2 = acc[nt][2] + bc0;
        float v3 = acc[nt][3] + bc1;
        if (RELU) {
            v0 = fmaxf(v0, 0.f); v1 = fmaxf(v1, 0.f);
            v2 = fmaxf(v2, 0.f); v3 = fmaxf(v3, 0.f);
        }
        O[(size_t)row * NOUT + col]           = v0;
        O[(size_t)row * NOUT + col + 1]       = v1;
        O[(size_t)(row + 8) * NOUT + col]     = v2;
        O[(size_t)(row + 8) * NOUT + col + 1] = v3;
    }
}

extern "C" void kernel_launch(void* const* d_in, const int* in_sizes, int n_in,
                              void* d_out, int out_size) {
    const float* x   = (const float*)d_in[0];
    const int*   cat = (const int*)  d_in[1];
    const float* W1  = (const float*)d_in[2];
    const float* b1  = (const float*)d_in[3];
    const float* W2  = (const float*)d_in[4];
    const float* b2  = (const float*)d_in[5];
    float*       out = (float*)d_out;

    build_perm_kernel<<<1, 32>>>(cat);

    dim3 grid(B_, HID / 64);
    // Layer 1: x @ W1 + b1, ReLU -> g_hidden
    catmlp_gemm<DIN, true,  false, true ><<<grid, 256>>>(x, W1, b1, cat, nullptr);
    // Layer 2: hidden @ W2 + b2 -> out
    catmlp_gemm<HID, false, true,  false><<<grid, 256>>>(nullptr, W2, b2, cat, out);
}

// round 5
// speedup vs baseline: 2.0408x; 2.0408x over previous
#include <cuda_runtime.h>
#include <cstdint>
#include <cstddef>

#define B_     128
#define T_     32
#define NCAT   32
#define MAXCH  56
#define BM     128
#define BN     256
#define BK     32
#define NS     3

#define A_STAGE_BYTES 16384                      // 128 rows x 32 k x 4B (swizzled)
#define B_STRIDE_W    264                        // 256 + 8 pad words (stride % 32 == 8)
#define B_STAGE_BYTES (32 * B_STRIDE_W * 4)      // 33792
#define STAGE_BYTES   (A_STAGE_BYTES + B_STAGE_BYTES)
#define SMEM_REQ      (NS * STAGE_BYTES)

__device__ float g_hidden[B_ * T_ * 1024];       // 16 MB fp32 hidden scratch
__device__ int   g_chunk_b[64][4];
__device__ int   g_chunk_cat[64];
__device__ int   g_nchunks;

// ---------------------------------------------------------------------------
// Build m-chunks: groups of up to 4 same-category batches (pad by replication).
// Duplicated rows recompute identical values -> benign duplicate stores.
// ---------------------------------------------------------------------------
__global__ void build_chunks(const int* __restrict__ cat_ids) {
    __shared__ int cats[B_];
    int t = threadIdx.x;
    if (t < B_) cats[t] = cat_ids[t];
    __syncthreads();
    if (t < NCAT) {
        int n = 0;
        for (int b = 0; b < B_; b++) n += (cats[b] == t);
        int myc = (n + 3) >> 2;
        int inc = myc;                            // warp inclusive scan (warp 0)
        for (int d = 1; d < 32; d <<= 1) {
            int v = __shfl_up_sync(0xffffffffu, inc, d);
            if (t >= d) inc += v;
        }
        int base = inc - myc;
        if (t == 31) g_nchunks = inc;
        int m = 0, last = 0;
        for (int b = 0; b < B_; b++) {
            if (cats[b] == t) { g_chunk_b[base + (m >> 2)][m & 3] = b; last = b; m++; }
        }
        for (int j = 0; j < myc; j++) g_chunk_cat[base + j] = t;
        if (myc > 0) {
            int start = (n & 3) ? (n & 3) : 4;
            for (int q = start; q < 4; q++) g_chunk_b[base + myc - 1][q] = last;
        }
    }
}

__device__ __forceinline__ uint32_t f2tf32(float f) {
    uint32_t r;
    asm("cvt.rna.tf32.f32 %0, %1;" : "=r"(r) : "f"(f));
    return r;
}
__device__ __forceinline__ uint32_t smem_u32(const void* p) {
    uint32_t a;
    asm("{ .reg .u64 t; cvta.to.shared.u64 t, %1; cvt.u32.u64 %0, t; }" : "=r"(a) : "l"(p));
    return a;
}
__device__ __forceinline__ void cpa16(uint32_t d, const void* s) {
    asm volatile("cp.async.cg.shared.global [%0], [%1], 16;" :: "r"(d), "l"(s));
}

// ---------------------------------------------------------------------------
// One layer: out[chunk 128 rows x 256 n-tile] = act(A[128,K] @ W[cat][K,1024] + b)
// 256 threads = 8 warps (2M x 4N), warp tile 64x64, mma.sync.m16n8k8 tf32.
// ---------------------------------------------------------------------------
template <int K, bool RELU, bool IN_S, bool OUT_S>
__global__ __launch_bounds__(256, 1)
void catmlp_gemm(const float* __restrict__ gin, const float* __restrict__ Wt,
                 const float* __restrict__ bias, float* __restrict__ gout)
{
    const int bx = blockIdx.x;
    if (bx >= g_nchunks) return;

    extern __shared__ char smem[];
    const uint32_t sb = smem_u32(smem);

    __shared__ const float* rowp[BM];
    __shared__ int s_cb[4], s_cat;

    const int tid  = threadIdx.x;
    const int wid  = tid >> 5;
    const int lane = tid & 31;
    const int wm   = (wid >> 2) * 64;            // 0 / 64
    const int wn   = (wid & 3) * 64;             // 0..192
    const int lg   = lane >> 2;
    const int lr   = lane & 3;
    const int sw   = lg << 2;                    // A swizzle for this lane

    if (tid < 4)  s_cb[tid] = g_chunk_b[bx][tid];
    if (tid == 4) s_cat = g_chunk_cat[bx];
    __syncthreads();

    const float* in_base = IN_S ? (const float*)g_hidden : gin;
    if (tid < BM) {
        int b = s_cb[tid >> 5];
        rowp[tid] = in_base + ((size_t)b * T_ + (tid & 31)) * (size_t)K;
    }
    const int cat = s_cat;
    const float* Wc = Wt + (size_t)cat * K * 1024;
    const int n0 = blockIdx.y * BN;
    __syncthreads();

    constexpr int NC = K / BK;

    auto stage = [&](int ch) {
        const int k0 = ch * BK;
        const uint32_t base = sb + (ch % NS) * STAGE_BYTES;
        #pragma unroll
        for (int j = 0; j < 4; j++) {             // A: 1024 x 16B chunks / 256 thr
            int c   = tid + (j << 8);
            int row = c >> 3;
            int cw  = (c & 7) << 2;               // k word offset (0,4,...,28)
            uint32_t dst = base + ((row << 5) + (cw ^ ((row & 7) << 2))) * 4;
            cpa16(dst, rowp[row] + k0 + cw);
        }
        const uint32_t bbase = base + A_STAGE_BYTES;
        #pragma unroll
        for (int j = 0; j < 8; j++) {             // B: 2048 x 16B chunks / 256 thr
            int c  = tid + (j << 8);
            int k  = c >> 6;
            int nw = (c & 63) << 2;
            uint32_t dst = bbase + (k * B_STRIDE_W + nw) * 4;
            cpa16(dst, Wc + (size_t)(k0 + k) * 1024 + n0 + nw);
        }
        asm volatile("cp.async.commit_group;" ::: "memory");
    };

    stage(0);
    stage(1);

    float acc[4][8][4];
    #pragma unroll
    for (int mf = 0; mf < 4; mf++)
        #pragma unroll
        for (int nf = 0; nf < 8; nf++)
            #pragma unroll
            for (int q = 0; q < 4; q++) acc[mf][nf][q] = 0.f;

    for (int i = 0; i < NC; i++) {
        if (i + 2 < NC) asm volatile("cp.async.wait_group 1;" ::: "memory");
        else            asm volatile("cp.async.wait_group 0;" ::: "memory");
        __syncthreads();

        const char* sbuf = smem + (size_t)(i % NS) * STAGE_BYTES;
        const float* As = (const float*)sbuf;
        const float* Bs = (const float*)(sbuf + A_STAGE_BYTES);

        #pragma unroll
        for (int ks = 0; ks < 4; ks++) {
            const int c0 = ((ks << 3) | lr) ^ sw; // swizzled k-col
            const int c1 = c0 ^ 4;
            uint32_t ua[4][4];
            #pragma unroll
            for (int mf = 0; mf < 4; mf++) {
                const int r0 = wm + mf * 16 + lg;
                ua[mf][0] = f2tf32(As[(r0     ) * 32 + c0]);
                ua[mf][1] = f2tf32(As[(r0 + 8 ) * 32 + c0]);
                ua[mf][2] = f2tf32(As[(r0     ) * 32 + c1]);
                ua[mf][3] = f2tf32(As[(r0 + 8 ) * 32 + c1]);
            }
            uint32_t ub[8][2];
            const int kb0 = ((ks << 3) + lr) * B_STRIDE_W;
            const int kb1 = kb0 + 4 * B_STRIDE_W;
            const int nb  = wn + lg;
            #pragma unroll
            for (int nf = 0; nf < 8; nf++) {
                ub[nf][0] = f2tf32(Bs[kb0 + nb + nf * 8]);
                ub[nf][1] = f2tf32(Bs[kb1 + nb + nf * 8]);
            }
            #pragma unroll
            for (int mf = 0; mf < 4; mf++)
                #pragma unroll
                for (int nf = 0; nf < 8; nf++)
                    asm volatile(
                        "mma.sync.aligned.m16n8k8.row.col.f32.tf32.tf32.f32 "
                        "{%0,%1,%2,%3}, {%4,%5,%6,%7}, {%8,%9}, {%0,%1,%2,%3};"
                        : "+f"(acc[mf][nf][0]), "+f"(acc[mf][nf][1]),
                          "+f"(acc[mf][nf][2]), "+f"(acc[mf][nf][3])
                        : "r"(ua[mf][0]), "r"(ua[mf][1]), "r"(ua[mf][2]), "r"(ua[mf][3]),
                          "r"(ub[nf][0]), "r"(ub[nf][1]));
        }

        if (i + 2 < NC) stage(i + 2);
    }

    // Epilogue: +bias, optional ReLU, fp32 stores (float2 per fragment row)
    float* ob = OUT_S ? (float*)g_hidden : gout;
    const float* brow = bias + (size_t)cat * 1024 + n0;
    float2 bb[8];
    #pragma unroll
    for (int nf = 0; nf < 8; nf++)
        bb[nf] = *(const float2*)(brow + wn + nf * 8 + lr * 2);

    #pragma unroll
    for (int mf = 0; mf < 4; mf++) {
        const int r0 = wm + mf * 16 + lg;
        const int r1 = r0 + 8;
        const int batch = s_cb[r0 >> 5];          // r0, r1 share the 32-row slab
        float* o0 = ob + ((size_t)batch * T_ + (r0 & 31)) * 1024 + n0;
        float* o1 = ob + ((size_t)batch * T_ + (r1 & 31)) * 1024 + n0;
        #pragma unroll
        for (int nf = 0; nf < 8; nf++) {
            const int col = wn + nf * 8 + lr * 2;
            float2 v0, v1;
            v0.x = acc[mf][nf][0] + bb[nf].x;
            v0.y = acc[mf][nf][1] + bb[nf].y;
            v1.x = acc[mf][nf][2] + bb[nf].x;
            v1.y = acc[mf][nf][3] + bb[nf].y;
            if (RELU) {
                v0.x = fmaxf(v0.x, 0.f); v0.y = fmaxf(v0.y, 0.f);
                v1.x = fmaxf(v1.x, 0.f); v1.y = fmaxf(v1.y, 0.f);
            }
            *(float2*)(o0 + col) = v0;
            *(float2*)(o1 + col) = v1;
        }
    }
}

// ---------------------------------------------------------------------------
extern "C" void kernel_launch(void* const* d_in, const int* in_sizes, int n_in,
                              void* d_out, int out_size) {
    const float* x   = (const float*)d_in[0];
    const int*   cat = (const int*)  d_in[1];
    const float* W1  = (const float*)d_in[2];
    const float* b1  = (const float*)d_in[3];
    const float* W2  = (const float*)d_in[4];
    const float* b2  = (const float*)d_in[5];
    float*       out = (float*)d_out;

    cudaFuncSetAttribute(catmlp_gemm<1536, true,  false, true >,
                         cudaFuncAttributeMaxDynamicSharedMemorySize, SMEM_REQ);
    cudaFuncSetAttribute(catmlp_gemm<1024, false, true,  false>,
                         cudaFuncAttributeMaxDynamicSharedMemorySize, SMEM_REQ);

    build_chunks<<<1, 128>>>(cat);

    dim3 grid(MAXCH, 1024 / BN);
    catmlp_gemm<1536, true,  false, true ><<<grid, 256, SMEM_REQ>>>(x,  W1, b1, nullptr);
    catmlp_gemm<1024, false, true,  false><<<grid, 256, SMEM_REQ>>>(nullptr, W2, b2, out);
}